// round 1
// baseline (speedup 1.0000x reference)
#include <cuda_runtime.h>
#include <math.h>

#define LSTEPS 64
#define BDIM   512
#define HDIM   1024
#define SDIM   128
#define ADIM   32
#define NDIM   1024
#define EDIM   1024

#define BH ((size_t)BDIM * HDIM)        // 524288
#define BS ((size_t)BDIM * SDIM)        // 65536
#define LBH ((size_t)LSTEPS * BH)       // 33554432
#define LBS ((size_t)LSTEPS * BS)       // 4194304

// ------------- scratch (device globals; no allocation) ------------------
__device__ float g_xa[BDIM * (SDIM + ADIM)];
__device__ float g_x [BDIM * HDIM];
__device__ float g_gi[BDIM * 3 * HDIM];
__device__ float g_gh[BDIM * 3 * HDIM];
__device__ float g_pe[BDIM * NDIM];
__device__ float g_hq[BDIM * (HDIM + EDIM)];
__device__ float g_qe[BDIM * NDIM];

struct GemmArgs {
    const float* A;     // M x K, row-major (stride K)
    const float* W;     // N x K, row-major (stride K)  -> C = A @ W^T
    const float* bias;  // N
    float*       C;     // EPI 0/1: M x N.  EPI 2: mean out (M x N/2)
    float*       C2;    // EPI 2: std out (M x N/2)
    int          K;
};

__device__ __forceinline__ float sigmoidf_(float x) { return 1.0f / (1.0f + expf(-x)); }
__device__ __forceinline__ float softplusf_(float x) {
    return fmaxf(x, 0.0f) + log1pf(expf(-fabsf(x)));
}

// ---------------- generic NT SGEMM, double-buffered smem -----------------
// EPI: 0 = bias, 1 = bias+relu, 2 = bias then split mean / softplus(std)+0.1
template<int BM, int BN, int BK, int TM, int TN, int EPI>
__global__ __launch_bounds__((BM / TM) * (BN / TN))
void gemm_nt(GemmArgs ga0, GemmArgs ga1, int M, int N)
{
    static_assert(BK == 16, "BK must be 16");
    constexpr int THREADS = (BM / TM) * (BN / TN);
    constexpr int TX = BN / TN;
    constexpr int LA = (BM * BK) / (THREADS * 4);
    constexpr int LB = (BN * BK) / (THREADS * 4);
    constexpr int PAD = 4;

    const GemmArgs ga = (blockIdx.z == 0) ? ga0 : ga1;
    const float* __restrict__ A    = ga.A;
    const float* __restrict__ W    = ga.W;
    const float* __restrict__ bias = ga.bias;
    const int K = ga.K;

    __shared__ float As[2][BK][BM + PAD];
    __shared__ float Bs[2][BK][BN + PAD];

    const int tid = threadIdx.x;
    const int tx  = tid % TX;
    const int ty  = tid / TX;
    const int bm  = blockIdx.y * BM;
    const int bn  = blockIdx.x * BN;

    float acc[TM][TN];
#pragma unroll
    for (int i = 0; i < TM; i++)
#pragma unroll
        for (int j = 0; j < TN; j++) acc[i][j] = 0.0f;

    float4 ra[LA], rb[LB];
    const int kTiles = K / BK;

    // load tile 0
#pragma unroll
    for (int i = 0; i < LA; i++) {
        int idx = tid + i * THREADS;
        int row = idx >> 2, kc = (idx & 3) << 2;
        ra[i] = *reinterpret_cast<const float4*>(A + (size_t)(bm + row) * K + kc);
    }
#pragma unroll
    for (int i = 0; i < LB; i++) {
        int idx = tid + i * THREADS;
        int row = idx >> 2, kc = (idx & 3) << 2;
        rb[i] = *reinterpret_cast<const float4*>(W + (size_t)(bn + row) * K + kc);
    }
#pragma unroll
    for (int i = 0; i < LA; i++) {
        int idx = tid + i * THREADS;
        int row = idx >> 2, kc = (idx & 3) << 2;
        As[0][kc + 0][row] = ra[i].x; As[0][kc + 1][row] = ra[i].y;
        As[0][kc + 2][row] = ra[i].z; As[0][kc + 3][row] = ra[i].w;
    }
#pragma unroll
    for (int i = 0; i < LB; i++) {
        int idx = tid + i * THREADS;
        int row = idx >> 2, kc = (idx & 3) << 2;
        Bs[0][kc + 0][row] = rb[i].x; Bs[0][kc + 1][row] = rb[i].y;
        Bs[0][kc + 2][row] = rb[i].z; Bs[0][kc + 3][row] = rb[i].w;
    }
    __syncthreads();

    for (int kt = 0; kt < kTiles; kt++) {
        const int buf = kt & 1;
        const bool more = (kt + 1 < kTiles);
        if (more) {
            const int ko = (kt + 1) * BK;
#pragma unroll
            for (int i = 0; i < LA; i++) {
                int idx = tid + i * THREADS;
                int row = idx >> 2, kc = (idx & 3) << 2;
                ra[i] = *reinterpret_cast<const float4*>(A + (size_t)(bm + row) * K + ko + kc);
            }
#pragma unroll
            for (int i = 0; i < LB; i++) {
                int idx = tid + i * THREADS;
                int row = idx >> 2, kc = (idx & 3) << 2;
                rb[i] = *reinterpret_cast<const float4*>(W + (size_t)(bn + row) * K + ko + kc);
            }
        }

#pragma unroll
        for (int k = 0; k < BK; k++) {
            float rm[TM], rn[TN];
#pragma unroll
            for (int i = 0; i < TM; i += 4) {
                float4 v = *reinterpret_cast<const float4*>(&As[buf][k][ty * TM + i]);
                rm[i] = v.x; rm[i + 1] = v.y; rm[i + 2] = v.z; rm[i + 3] = v.w;
            }
#pragma unroll
            for (int j = 0; j < TN; j += 4) {
                float4 v = *reinterpret_cast<const float4*>(&Bs[buf][k][tx * TN + j]);
                rn[j] = v.x; rn[j + 1] = v.y; rn[j + 2] = v.z; rn[j + 3] = v.w;
            }
#pragma unroll
            for (int i = 0; i < TM; i++)
#pragma unroll
                for (int j = 0; j < TN; j++)
                    acc[i][j] = fmaf(rm[i], rn[j], acc[i][j]);
        }

        if (more) {
            const int nb = buf ^ 1;
#pragma unroll
            for (int i = 0; i < LA; i++) {
                int idx = tid + i * THREADS;
                int row = idx >> 2, kc = (idx & 3) << 2;
                As[nb][kc + 0][row] = ra[i].x; As[nb][kc + 1][row] = ra[i].y;
                As[nb][kc + 2][row] = ra[i].z; As[nb][kc + 3][row] = ra[i].w;
            }
#pragma unroll
            for (int i = 0; i < LB; i++) {
                int idx = tid + i * THREADS;
                int row = idx >> 2, kc = (idx & 3) << 2;
                Bs[nb][kc + 0][row] = rb[i].x; Bs[nb][kc + 1][row] = rb[i].y;
                Bs[nb][kc + 2][row] = rb[i].z; Bs[nb][kc + 3][row] = rb[i].w;
            }
        }
        __syncthreads();
    }

    // epilogue
    const int half = N >> 1;
#pragma unroll
    for (int i = 0; i < TM; i++) {
        const int m = bm + ty * TM + i;
#pragma unroll
        for (int j = 0; j < TN; j++) {
            const int n = bn + tx * TN + j;
            float v = acc[i][j] + bias[n];
            if (EPI == 1) v = fmaxf(v, 0.0f);
            if (EPI == 2) {
                if (n < half) ga.C [(size_t)m * half + n]          = v;
                else          ga.C2[(size_t)m * half + (n - half)] = softplusf_(v) + 0.1f;
            } else {
                ga.C[(size_t)m * N + n] = v;
            }
        }
    }
}

// ----------------------------- glue kernels ------------------------------
__global__ void concat_xa_kernel(const float* __restrict__ spost,
                                 const float* __restrict__ nt,
                                 const float* __restrict__ act,
                                 float* __restrict__ xa)
{
    int idx = blockIdx.x * blockDim.x + threadIdx.x;
    const int KC = SDIM + ADIM;
    if (idx >= BDIM * KC) return;
    int m = idx / KC, k = idx % KC;
    float v = (k < SDIM) ? spost[m * SDIM + k] * nt[m]
                         : act[m * ADIM + (k - SDIM)];
    xa[idx] = v;
}

__global__ void concat_hq_kernel(const float* __restrict__ h,
                                 const float* __restrict__ obs,
                                 float* __restrict__ hq)
{
    int idx = blockIdx.x * blockDim.x + threadIdx.x;
    const int KC = HDIM + EDIM;
    if (idx >= BDIM * KC) return;
    int m = idx / KC, k = idx % KC;
    hq[idx] = (k < HDIM) ? h[m * HDIM + k] : obs[m * EDIM + (k - HDIM)];
}

__global__ void gru_gate_kernel(const float* __restrict__ hprev,
                                float* __restrict__ hnew)
{
    int idx = blockIdx.x * blockDim.x + threadIdx.x;
    if (idx >= BDIM * HDIM) return;
    int m = idx / HDIM, j = idx % HDIM;
    const float* gi = g_gi + (size_t)m * 3 * HDIM;
    const float* gh = g_gh + (size_t)m * 3 * HDIM;
    float r = sigmoidf_(gi[j]            + gh[j]);
    float z = sigmoidf_(gi[j + HDIM]     + gh[j + HDIM]);
    float n = tanhf    (gi[j + 2 * HDIM] + r * gh[j + 2 * HDIM]);
    hnew[idx] = (1.0f - z) * n + z * hprev[idx];
}

__global__ void state_kernel(const float* __restrict__ pm, const float* __restrict__ ps,
                             const float* __restrict__ n1, float* __restrict__ sprior,
                             const float* __restrict__ qm, const float* __restrict__ qs,
                             const float* __restrict__ n2, float* __restrict__ spost)
{
    int idx = blockIdx.x * blockDim.x + threadIdx.x;
    if (idx >= (int)BS) return;
    sprior[idx] = fmaf(ps[idx], n1[idx], pm[idx]);
    spost [idx] = fmaf(qs[idx], n2[idx], qm[idx]);
}

// ------------------------------ launch -----------------------------------
extern "C" void kernel_launch(void* const* d_in, const int* in_sizes, int n_in,
                              void* d_out, int out_size)
{
    (void)in_sizes; (void)n_in; (void)out_size;
    const float* prev_hidden = (const float*)d_in[0];
    const float* prev_state  = (const float*)d_in[1];
    const float* actions     = (const float*)d_in[2];
    const float* obs         = (const float*)d_in[3];
    const float* non_terms   = (const float*)d_in[4];
    const float* prior_noise = (const float*)d_in[5];
    const float* post_noise  = (const float*)d_in[6];
    const float* W_sa = (const float*)d_in[7];
    const float* b_sa = (const float*)d_in[8];
    const float* W_ih = (const float*)d_in[9];
    const float* W_hh = (const float*)d_in[10];
    const float* b_ih = (const float*)d_in[11];
    const float* b_hh = (const float*)d_in[12];
    const float* W_ep = (const float*)d_in[13];
    const float* b_ep = (const float*)d_in[14];
    const float* W_pr = (const float*)d_in[15];
    const float* b_pr = (const float*)d_in[16];
    const float* W_eq = (const float*)d_in[17];
    const float* b_eq = (const float*)d_in[18];
    const float* W_po = (const float*)d_in[19];
    const float* b_po = (const float*)d_in[20];

    float* out = (float*)d_out;
    const size_t off_pm     = LBH;
    const size_t off_ps     = LBH + 1 * LBS;
    const size_t off_sprior = LBH + 2 * LBS;
    const size_t off_qm     = LBH + 3 * LBS;
    const size_t off_qs     = LBH + 4 * LBS;
    const size_t off_spost  = LBH + 5 * LBS;

    float *xa, *x, *gi, *gh, *pe, *hq, *qe;
    cudaGetSymbolAddress((void**)&xa, g_xa);
    cudaGetSymbolAddress((void**)&x,  g_x);
    cudaGetSymbolAddress((void**)&gi, g_gi);
    cudaGetSymbolAddress((void**)&gh, g_gh);
    cudaGetSymbolAddress((void**)&pe, g_pe);
    cudaGetSymbolAddress((void**)&hq, g_hq);
    cudaGetSymbolAddress((void**)&qe, g_qe);

    for (int t = 0; t < LSTEPS; t++) {
        const float* spost_prev = (t == 0) ? prev_state
                                           : out + off_spost + (size_t)(t - 1) * BS;
        const float* hprev      = (t == 0) ? prev_hidden
                                           : out + (size_t)(t - 1) * BH;
        float* hnew = out + (size_t)t * BH;

        // x = relu([s_post*nt, a] @ W_sa^T + b_sa)
        {
            int n = BDIM * (SDIM + ADIM);
            concat_xa_kernel<<<(n + 255) / 256, 256>>>(
                spost_prev, non_terms + (size_t)t * BDIM,
                actions + (size_t)t * BDIM * ADIM, xa);
            GemmArgs a0{xa, W_sa, b_sa, x, nullptr, SDIM + ADIM};
            gemm_nt<64, 64, 16, 4, 4, 1><<<dim3(HDIM / 64, BDIM / 64, 1), 256>>>(
                a0, a0, BDIM, HDIM);
        }

        // gi = x @ W_ih^T + b_ih ;  gh = h @ W_hh^T + b_hh  (paired via z)
        {
            GemmArgs a0{x,     W_ih, b_ih, gi, nullptr, HDIM};
            GemmArgs a1{hprev, W_hh, b_hh, gh, nullptr, HDIM};
            gemm_nt<128, 128, 16, 8, 8, 0><<<dim3(3 * HDIM / 128, BDIM / 128, 2), 256>>>(
                a0, a1, BDIM, 3 * HDIM);
        }

        // GRU gates -> h_new (also output hiddens[t])
        gru_gate_kernel<<<((int)BH + 255) / 256, 256>>>(hprev, hnew);

        // hq = [h_new, obs_t]
        {
            int n = BDIM * (HDIM + EDIM);
            concat_hq_kernel<<<(n + 255) / 256, 256>>>(
                hnew, obs + (size_t)t * BDIM * EDIM, hq);
        }

        // pe = relu(h_new @ W_ep^T + b_ep) ; qe = relu(hq @ W_eq^T + b_eq)
        {
            GemmArgs a0{hnew, W_ep, b_ep, pe, nullptr, HDIM};
            GemmArgs a1{hq,   W_eq, b_eq, qe, nullptr, HDIM + EDIM};
            gemm_nt<64, 64, 16, 4, 4, 1><<<dim3(NDIM / 64, BDIM / 64, 2), 256>>>(
                a0, a1, BDIM, NDIM);
        }

        // prior / posterior heads: mean + softplus(std)+0.1, written to output
        float* pm_o = out + off_pm + (size_t)t * BS;
        float* ps_o = out + off_ps + (size_t)t * BS;
        float* qm_o = out + off_qm + (size_t)t * BS;
        float* qs_o = out + off_qs + (size_t)t * BS;
        {
            GemmArgs a0{pe, W_pr, b_pr, pm_o, ps_o, NDIM};
            GemmArgs a1{qe, W_po, b_po, qm_o, qs_o, NDIM};
            gemm_nt<64, 64, 16, 4, 4, 2><<<dim3(2 * SDIM / 64, BDIM / 64, 2), 256>>>(
                a0, a1, BDIM, 2 * SDIM);
        }

        // reparameterized states
        state_kernel<<<((int)BS + 255) / 256, 256>>>(
            pm_o, ps_o, prior_noise + (size_t)t * BS, out + off_sprior + (size_t)t * BS,
            qm_o, qs_o, post_noise  + (size_t)t * BS, out + off_spost  + (size_t)t * BS);
    }
}